// round 9
// baseline (speedup 1.0000x reference)
#include <cuda_runtime.h>
#include <cuda_bf16.h>

// ST-BIF multi-step neuron, T=4. HBM-bound streaming kernel.
// Each thread processes TWO float4 neuron-groups (at idx and idx+stepN/2),
// front-batching all 8 LDG.128 (MLP=8) to give the DRAM controller long
// read bursts before the store drain. Evict-first (.cs) on both directions.

#define POS_MAX 15.0f
#define NEG_MIN 0.0f
#define TSTEPS  4

__device__ __forceinline__ float bif_step(float& v, float& tc, float xv, float vth) {
    float H = v + xv;
    float spike;
    if (H >= vth && tc < POS_MAX)      spike = 1.0f;
    else if (H < 0.0f && tc > NEG_MIN) spike = -1.0f;
    else                               spike = 0.0f;
    v  = H - spike * vth;
    tc = tc + spike;
    return spike * vth;
}

__device__ __forceinline__ float4 bif_group4(float4 v[1], float4 tc[1], float4 xs, float vth) {
    float4 o;
    o.x = bif_step(v[0].x, tc[0].x, xs.x, vth);
    o.y = bif_step(v[0].y, tc[0].y, xs.y, vth);
    o.z = bif_step(v[0].z, tc[0].z, xs.z, vth);
    o.w = bif_step(v[0].w, tc[0].w, xs.w, vth);
    return o;
}

__global__ void __launch_bounds__(256)
st_bif_ms_kernel(const float* __restrict__ x,
                 const float* __restrict__ qth_ptr,
                 float* __restrict__ out,
                 int half,    // stepN / 2
                 int stepN)   // elements per timestep (B*L*D)
{
    int idx = (blockIdx.x * blockDim.x + threadIdx.x) * 4;
    if (idx >= half) return;
    int jdx = idx + half;

    const float vth = __ldg(qth_ptr);
    const size_t sN = (size_t)stepN;

    // Front-batch all 8 timestep loads: MLP=8 independent LDG.128
    float4 a0 = __ldcs(reinterpret_cast<const float4*>(x + idx));
    float4 a1 = __ldcs(reinterpret_cast<const float4*>(x + idx + sN));
    float4 a2 = __ldcs(reinterpret_cast<const float4*>(x + idx + 2 * sN));
    float4 a3 = __ldcs(reinterpret_cast<const float4*>(x + idx + 3 * sN));
    float4 b0 = __ldcs(reinterpret_cast<const float4*>(x + jdx));
    float4 b1 = __ldcs(reinterpret_cast<const float4*>(x + jdx + sN));
    float4 b2 = __ldcs(reinterpret_cast<const float4*>(x + jdx + 2 * sN));
    float4 b3 = __ldcs(reinterpret_cast<const float4*>(x + jdx + 3 * sN));

    // Group A
    {
        float4 v  = make_float4(0.5f * vth, 0.5f * vth, 0.5f * vth, 0.5f * vth);
        float4 tc = make_float4(0.f, 0.f, 0.f, 0.f);
        float4 o;
        o = bif_group4(&v, &tc, a0, vth);
        __stcs(reinterpret_cast<float4*>(out + idx), o);
        o = bif_group4(&v, &tc, a1, vth);
        __stcs(reinterpret_cast<float4*>(out + idx + sN), o);
        o = bif_group4(&v, &tc, a2, vth);
        __stcs(reinterpret_cast<float4*>(out + idx + 2 * sN), o);
        o = bif_group4(&v, &tc, a3, vth);
        __stcs(reinterpret_cast<float4*>(out + idx + 3 * sN), o);
    }
    // Group B
    {
        float4 v  = make_float4(0.5f * vth, 0.5f * vth, 0.5f * vth, 0.5f * vth);
        float4 tc = make_float4(0.f, 0.f, 0.f, 0.f);
        float4 o;
        o = bif_group4(&v, &tc, b0, vth);
        __stcs(reinterpret_cast<float4*>(out + jdx), o);
        o = bif_group4(&v, &tc, b1, vth);
        __stcs(reinterpret_cast<float4*>(out + jdx + sN), o);
        o = bif_group4(&v, &tc, b2, vth);
        __stcs(reinterpret_cast<float4*>(out + jdx + 2 * sN), o);
        o = bif_group4(&v, &tc, b3, vth);
        __stcs(reinterpret_cast<float4*>(out + jdx + 3 * sN), o);
    }
}

extern "C" void kernel_launch(void* const* d_in, const int* in_sizes, int n_in,
                              void* d_out, int out_size) {
    const float* x   = (const float*)d_in[0];   // [T*B, L, D] fp32
    const float* qth = (const float*)d_in[1];   // scalar fp32
    float* out = (float*)d_out;

    int total = in_sizes[0];         // T*B*L*D = 50,331,648
    int stepN = total / TSTEPS;      // B*L*D   = 12,582,912
    int half  = stepN / 2;           // 6,291,456 (divisible by 4)

    int threads = half / 4;          // one thread per 2 float4 groups
    int tpb = 256;
    int blocks = (threads + tpb - 1) / tpb;   // 6144
    st_bif_ms_kernel<<<blocks, tpb>>>(x, qth, out, half, stepN);
}

// round 10
// speedup vs baseline: 1.0040x; 1.0040x over previous
#include <cuda_runtime.h>
#include <cuda_bf16.h>

// ST-BIF multi-step neuron, T=4 timesteps. HBM/LTS-bound streaming kernel:
// 192 MiB read + 192 MiB write, zero reuse. Measured at the LTS chip cap
// (~7.1 TB/s combined) across three structural variants -> this is the
// roofline configuration: 1 float4 per thread, loads front-batched (MLP=4),
// per-timestep stores, evict-first (.cs) both directions.

#define POS_MAX 15.0f
#define NEG_MIN 0.0f
#define TSTEPS  4

__device__ __forceinline__ float bif_step(float& v, float& tc, float xv, float vth) {
    float H = v + xv;
    float spike;
    if (H >= vth && tc < POS_MAX)      spike = 1.0f;
    else if (H < 0.0f && tc > NEG_MIN) spike = -1.0f;
    else                               spike = 0.0f;
    v  = H - spike * vth;
    tc = tc + spike;
    return spike * vth;
}

__global__ void __launch_bounds__(256, 8)
st_bif_ms_kernel(const float* __restrict__ x,
                 const float* __restrict__ qth_ptr,
                 float* __restrict__ out,
                 int stepN)  // elements per timestep (B*L*D); grid covers it exactly
{
    size_t idx = ((size_t)blockIdx.x * blockDim.x + threadIdx.x) * 4;
    const size_t sN = (size_t)stepN;

    const float vth = __ldg(qth_ptr);

    const float4* xin = reinterpret_cast<const float4*>(x + idx);
    float4*       xo  = reinterpret_cast<float4*>(out + idx);
    const size_t  s4  = sN / 4;   // stride in float4 units

    // Front-batch all 4 timestep loads: 4 independent LDG.128 (MLP=4)
    float4 xs0 = __ldcs(xin);
    float4 xs1 = __ldcs(xin + s4);
    float4 xs2 = __ldcs(xin + 2 * s4);
    float4 xs3 = __ldcs(xin + 3 * s4);

    float v[4]  = {0.5f * vth, 0.5f * vth, 0.5f * vth, 0.5f * vth};
    float tc[4] = {0.f, 0.f, 0.f, 0.f};
    float4 o;

    // t = 0
    o.x = bif_step(v[0], tc[0], xs0.x, vth);
    o.y = bif_step(v[1], tc[1], xs0.y, vth);
    o.z = bif_step(v[2], tc[2], xs0.z, vth);
    o.w = bif_step(v[3], tc[3], xs0.w, vth);
    __stcs(xo, o);

    // t = 1
    o.x = bif_step(v[0], tc[0], xs1.x, vth);
    o.y = bif_step(v[1], tc[1], xs1.y, vth);
    o.z = bif_step(v[2], tc[2], xs1.z, vth);
    o.w = bif_step(v[3], tc[3], xs1.w, vth);
    __stcs(xo + s4, o);

    // t = 2
    o.x = bif_step(v[0], tc[0], xs2.x, vth);
    o.y = bif_step(v[1], tc[1], xs2.y, vth);
    o.z = bif_step(v[2], tc[2], xs2.z, vth);
    o.w = bif_step(v[3], tc[3], xs2.w, vth);
    __stcs(xo + 2 * s4, o);

    // t = 3
    o.x = bif_step(v[0], tc[0], xs3.x, vth);
    o.y = bif_step(v[1], tc[1], xs3.y, vth);
    o.z = bif_step(v[2], tc[2], xs3.z, vth);
    o.w = bif_step(v[3], tc[3], xs3.w, vth);
    __stcs(xo + 3 * s4, o);
}

extern "C" void kernel_launch(void* const* d_in, const int* in_sizes, int n_in,
                              void* d_out, int out_size) {
    const float* x   = (const float*)d_in[0];   // [T*B, L, D] fp32
    const float* qth = (const float*)d_in[1];   // scalar fp32
    float* out = (float*)d_out;

    int total = in_sizes[0];         // T*B*L*D = 50,331,648
    int stepN = total / TSTEPS;      // B*L*D   = 12,582,912 = 12288 * 256 * 4

    int threads = stepN / 4;         // one thread per float4
    int tpb = 256;
    int blocks = threads / tpb;      // exact: 12288
    st_bif_ms_kernel<<<blocks, tpb>>>(x, qth, out, stepN);
}

// round 11
// speedup vs baseline: 1.0101x; 1.0060x over previous
#include <cuda_runtime.h>
#include <cuda_bf16.h>

// ST-BIF multi-step neuron, T=4 timesteps. HBM/LTS-bound streaming kernel:
// 192 MiB read + 192 MiB write, zero reuse -> at the path-independent LTS
// chip cap (~7.1 TB/s combined R+W). Best-measured configuration (R7):
//  - 32-bit thread indexing (64-bit arithmetic regressed DRAM% in R9)
//  - 1 float4 per thread, 4 front-batched LDG.128 (MLP=4)
//  - per-timestep stores to keep live range small (regs=32, occ ~83%)
//  - evict-first (.cs) hints both directions

#define POS_MAX 15.0f
#define NEG_MIN 0.0f
#define TSTEPS  4

__device__ __forceinline__ float bif_step(float& v, float& tc, float xv, float vth) {
    float H = v + xv;
    float spike;
    if (H >= vth && tc < POS_MAX)      spike = 1.0f;
    else if (H < 0.0f && tc > NEG_MIN) spike = -1.0f;
    else                               spike = 0.0f;
    v  = H - spike * vth;
    tc = tc + spike;
    return spike * vth;
}

__global__ void __launch_bounds__(256, 8)
st_bif_ms_kernel(const float* __restrict__ x,
                 const float* __restrict__ qth_ptr,
                 float* __restrict__ out,
                 int stepN)  // elements per timestep (B*L*D)
{
    int idx = (blockIdx.x * blockDim.x + threadIdx.x) * 4;
    if (idx >= stepN) return;

    const float vth = __ldg(qth_ptr);

    // Front-batch all 4 timestep loads (MLP=4), streaming / evict-first.
    const float4* p0 = reinterpret_cast<const float4*>(x + idx);
    const float4* p1 = reinterpret_cast<const float4*>(x + idx + (size_t)stepN);
    const float4* p2 = reinterpret_cast<const float4*>(x + idx + (size_t)2 * stepN);
    const float4* p3 = reinterpret_cast<const float4*>(x + idx + (size_t)3 * stepN);
    float4 xs0 = __ldcs(p0);
    float4 xs1 = __ldcs(p1);
    float4 xs2 = __ldcs(p2);
    float4 xs3 = __ldcs(p3);

    float v[4], tc[4];
    #pragma unroll
    for (int j = 0; j < 4; j++) { v[j] = 0.5f * vth; tc[j] = 0.0f; }

    float4 o;

    // t = 0: compute then store immediately (shrinks live range -> fewer regs)
    o.x = bif_step(v[0], tc[0], xs0.x, vth);
    o.y = bif_step(v[1], tc[1], xs0.y, vth);
    o.z = bif_step(v[2], tc[2], xs0.z, vth);
    o.w = bif_step(v[3], tc[3], xs0.w, vth);
    __stcs(reinterpret_cast<float4*>(out + idx), o);

    // t = 1
    o.x = bif_step(v[0], tc[0], xs1.x, vth);
    o.y = bif_step(v[1], tc[1], xs1.y, vth);
    o.z = bif_step(v[2], tc[2], xs1.z, vth);
    o.w = bif_step(v[3], tc[3], xs1.w, vth);
    __stcs(reinterpret_cast<float4*>(out + idx + (size_t)stepN), o);

    // t = 2
    o.x = bif_step(v[0], tc[0], xs2.x, vth);
    o.y = bif_step(v[1], tc[1], xs2.y, vth);
    o.z = bif_step(v[2], tc[2], xs2.z, vth);
    o.w = bif_step(v[3], tc[3], xs2.w, vth);
    __stcs(reinterpret_cast<float4*>(out + idx + (size_t)2 * stepN), o);

    // t = 3
    o.x = bif_step(v[0], tc[0], xs3.x, vth);
    o.y = bif_step(v[1], tc[1], xs3.y, vth);
    o.z = bif_step(v[2], tc[2], xs3.z, vth);
    o.w = bif_step(v[3], tc[3], xs3.w, vth);
    __stcs(reinterpret_cast<float4*>(out + idx + (size_t)3 * stepN), o);
}

extern "C" void kernel_launch(void* const* d_in, const int* in_sizes, int n_in,
                              void* d_out, int out_size) {
    const float* x   = (const float*)d_in[0];   // [T*B, L, D] fp32
    const float* qth = (const float*)d_in[1];   // scalar fp32
    float* out = (float*)d_out;

    int total = in_sizes[0];         // T*B*L*D = 50,331,648
    int stepN = total / TSTEPS;      // B*L*D   = 12,582,912 (divisible by 4)

    int threads = stepN / 4;         // one thread per float4 per timestep
    int tpb = 256;
    int blocks = (threads + tpb - 1) / tpb;   // 12288
    st_bif_ms_kernel<<<blocks, tpb>>>(x, qth, out, stepN);
}